// round 14
// baseline (speedup 1.0000x reference)
#include <cuda_runtime.h>

#define D 64
#define GMAX 64
#define NMAX 100000
#define EMAX 1250000

// ---- scratch (device globals). float4 => 16B alignment. ----
__device__ float4 g_h4[NMAX * D / 4];     // h' = (x @ W) * dis[row]
__device__ float4 g_buf04[NMAX * D / 4];  // layer ping-pong
__device__ float4 g_buf14[NMAX * D / 4];
__device__ int   g_degE[NMAX];            // real in-degree (no self loop)
__device__ int   g_start[NMAX];           // CSR exclusive offsets
__device__ int   g_cursor[NMAX];          // fill cursors
__device__ int   g_csr[EMAX];             // src ids grouped by dst
__device__ int   g_bsum[256];             // scan block sums
__device__ int   g_boff[256];             // scan block offsets
__device__ float g_dis[NMAX];
__device__ float g_cnt[GMAX];
__device__ float g_gmax[GMAX * D];
__device__ float g_gsum[GMAX * D];

#define g_h ((float*)g_h4)

// ---- init ----
__global__ void k_init(float* __restrict__ out_graph, int n) {
    int i = blockIdx.x * blockDim.x + threadIdx.x;
    if (i < n) g_degE[i] = 0;
    if (i < GMAX) g_cnt[i] = 0.0f;
    if (i < GMAX * D) { g_gmax[i] = 0.0f; g_gsum[i] = 0.0f; }
    if (i < GMAX * 2 * D) out_graph[i] = 0.0f;
}

// ---- in-degree over destinations (int) ----
__global__ void k_deg(const int* __restrict__ ei, int e) {
    int i = blockIdx.x * blockDim.x + threadIdx.x;
    if (i < e) atomicAdd(&g_degE[ei[e + i]], 1);
}

// ---- dis = rsqrt(degE + 1); per-graph node counts ----
__global__ void k_dis(const int* __restrict__ batch, int n) {
    int i = blockIdx.x * blockDim.x + threadIdx.x;
    if (i < n) {
        g_dis[i] = rsqrtf((float)(g_degE[i] + 1));
        atomicAdd(&g_cnt[batch[i]], 1.0f);
    }
}

// ---- deterministic 2-level exclusive scan of g_degE -> g_start ----
__global__ void k_scan1(int n) {
    __shared__ int s[512];
    int i = blockIdx.x * 512 + threadIdx.x;
    int v = (i < n) ? g_degE[i] : 0;
    s[threadIdx.x] = v;
    __syncthreads();
    for (int off = 1; off < 512; off <<= 1) {
        int t = (threadIdx.x >= off) ? s[threadIdx.x - off] : 0;
        __syncthreads();
        s[threadIdx.x] += t;
        __syncthreads();
    }
    if (i < n) g_start[i] = s[threadIdx.x] - v;   // exclusive
    if (threadIdx.x == 511) g_bsum[blockIdx.x] = s[511];
}
__global__ void k_scan2(int nb) {
    __shared__ int s[256];
    int v = (threadIdx.x < nb) ? g_bsum[threadIdx.x] : 0;
    s[threadIdx.x] = v;
    __syncthreads();
    for (int off = 1; off < 256; off <<= 1) {
        int t = (threadIdx.x >= off) ? s[threadIdx.x - off] : 0;
        __syncthreads();
        s[threadIdx.x] += t;
        __syncthreads();
    }
    if (threadIdx.x < nb) g_boff[threadIdx.x] = s[threadIdx.x] - v;
}
__global__ void k_scan3(int n) {
    int i = blockIdx.x * blockDim.x + threadIdx.x;
    if (i < n) {
        int st = g_start[i] + g_boff[i >> 9];
        g_start[i] = st;
        g_cursor[i] = st;
    }
}

// ---- CSR fill: group src by dst (order within node nondeterministic; sum-safe) ----
__global__ void k_fill(const int* __restrict__ ei, int e) {
    int i = blockIdx.x * blockDim.x + threadIdx.x;
    if (i >= e) return;
    int dst = ei[e + i];
    int pos = atomicAdd(&g_cursor[dst], 1);
    g_csr[pos] = ei[i];
}

// ---- h' = (x @ W) * dis[row] ----
// 128 rows/block, 128 threads. Thread (r, c) computes rows r, r+32, r+64, r+96,
// contiguous cols [16c, 16c+16). Per k: 4 xs scalar LDS + 4 ws LDS.128 feed
// 64 FMAs across 4 INDEPENDENT row-chains (LDS/FMA 0.125; R5's serial-chain
// failure mode avoided by the 4-way row ILP). xs rotation pattern unchanged.
__global__ void k_gemm(const float* __restrict__ x, const float* __restrict__ W, int n) {
    __shared__ float xs[128 * 64];    // 32KB, rotated rows
    __shared__ float4 ws4[64 * 16];   // 16KB -> total 48KB = limit
    int t = threadIdx.x;              // 0..127
    int R0 = blockIdx.x * 128;
    int rows = min(128, n - R0);

    for (int i = t; i < 64 * 16; i += 128)
        ws4[i] = ((const float4*)W)[i];
    for (int i = t; i < rows * 16; i += 128) {
        int rr = i >> 4, c4 = i & 15;
        int roff = ((c4 * 4 + rr * 4) & 63);          // rotated, 16B-aligned
        *(float4*)(xs + rr * 64 + roff) = *((const float4*)(x + (size_t)(R0 + rr) * 64) + c4);
    }
    __syncthreads();

    int r = t >> 2;      // 0..31 -> rows r, r+32, r+64, r+96
    int c = t & 3;       // 0..3  -> cols [16c, 16c+16)
    int rot = (r * 4) & 63;
    const float* x0 = xs + r * 64;
    const float* x1 = xs + (r + 32) * 64;
    const float* x2 = xs + (r + 64) * 64;
    const float* x3 = xs + (r + 96) * 64;

    float4 a0[4], a1[4], a2[4], a3[4];   // [row][col-quad]
#pragma unroll
    for (int j = 0; j < 4; j++) {
        a0[j] = make_float4(0.f, 0.f, 0.f, 0.f);
        a1[j] = make_float4(0.f, 0.f, 0.f, 0.f);
        a2[j] = make_float4(0.f, 0.f, 0.f, 0.f);
        a3[j] = make_float4(0.f, 0.f, 0.f, 0.f);
    }
#pragma unroll 16
    for (int k = 0; k < 64; k++) {
        int koff = (k + rot) & 63;
        float xv0 = x0[koff];
        float xv1 = x1[koff];
        float xv2 = x2[koff];
        float xv3 = x3[koff];
        const float4* wr = ws4 + k * 16 + c * 4;
#pragma unroll
        for (int j = 0; j < 4; j++) {
            float4 w = wr[j];
            a0[j].x += xv0 * w.x; a0[j].y += xv0 * w.y; a0[j].z += xv0 * w.z; a0[j].w += xv0 * w.w;
            a1[j].x += xv1 * w.x; a1[j].y += xv1 * w.y; a1[j].z += xv1 * w.z; a1[j].w += xv1 * w.w;
            a2[j].x += xv2 * w.x; a2[j].y += xv2 * w.y; a2[j].z += xv2 * w.z; a2[j].w += xv2 * w.w;
            a3[j].x += xv3 * w.x; a3[j].y += xv3 * w.y; a3[j].z += xv3 * w.z; a3[j].w += xv3 * w.w;
        }
    }
#pragma unroll
    for (int q = 0; q < 4; q++) {
        int rr = r + q * 32;
        if (rr < rows) {
            int gr = R0 + rr;
            float s = g_dis[gr];
            float4* hp = (float4*)(g_h + (size_t)gr * 64) + c * 4;
            const float4* a = (q == 0) ? a0 : (q == 1) ? a1 : (q == 2) ? a2 : a3;
#pragma unroll
            for (int j = 0; j < 4; j++) {
                float4 v = a[j];
                hp[j] = make_float4(v.x * s, v.y * s, v.z * s, v.w * s);
            }
        }
    }
}

// ---- fused gather + epilogue + pooling ----
// EXACT R12/R13 version (proven). 16 nodes/block x 16 threads/node.
__global__ void k_gather(const float* __restrict__ b, const int* __restrict__ batch,
                         float* __restrict__ xout, int n) {
    int t = threadIdx.x;
    int ln = t & 15;          // float4 lane (cols 4*ln .. 4*ln+3)
    int nr = t >> 4;          // node-in-block 0..15
    int node = blockIdx.x * 16 + nr;

    float4 acc = {0.f, 0.f, 0.f, 0.f};
    float4 out = {0.f, 0.f, 0.f, 0.f};
    if (node < n) {
        acc = g_h4[(size_t)node * 16 + ln];           // self loop (already *dis[node])
        float4 accB = {0.f, 0.f, 0.f, 0.f};
        int st = g_start[node];
        int end = st + g_degE[node];
        int k = st;
        for (; k + 3 < end; k += 4) {
            int s0 = g_csr[k],     s1 = g_csr[k + 1];
            int s2 = g_csr[k + 2], s3 = g_csr[k + 3];
            float4 v0 = g_h4[(size_t)s0 * 16 + ln];
            float4 v1 = g_h4[(size_t)s1 * 16 + ln];
            float4 v2 = g_h4[(size_t)s2 * 16 + ln];
            float4 v3 = g_h4[(size_t)s3 * 16 + ln];
            acc.x += v0.x + v1.x;  accB.x += v2.x + v3.x;
            acc.y += v0.y + v1.y;  accB.y += v2.y + v3.y;
            acc.z += v0.z + v1.z;  accB.z += v2.z + v3.z;
            acc.w += v0.w + v1.w;  accB.w += v2.w + v3.w;
        }
        for (; k < end; k++) {
            int s0 = g_csr[k];
            float4 v0 = g_h4[(size_t)s0 * 16 + ln];
            acc.x += v0.x; acc.y += v0.y; acc.z += v0.z; acc.w += v0.w;
        }
        acc.x += accB.x; acc.y += accB.y; acc.z += accB.z; acc.w += accB.w;

        float d = g_dis[node];
        float4 bb = ((const float4*)b)[ln];
        out.x = fmaxf(fmaf(d, acc.x, bb.x), 0.f);
        out.y = fmaxf(fmaf(d, acc.y, bb.y), 0.f);
        out.z = fmaxf(fmaf(d, acc.z, bb.z), 0.f);
        out.w = fmaxf(fmaf(d, acc.w, bb.w), 0.f);
        ((float4*)xout)[(size_t)node * 16 + ln] = out;
    }

    // pooling
    int R0 = blockIdx.x * 16;
    int last = min(R0 + 15, n - 1);
    int gfirst = batch[R0];
    int glast = batch[last];

    if (gfirst == glast) {
        __shared__ float4 ssum[16][16];
        __shared__ float4 smax[16][16];
        ssum[nr][ln] = out;               // out==0 for node>=n: identity for sum, safe for relu-max
        smax[nr][ln] = out;
        __syncthreads();
#pragma unroll
        for (int off = 8; off > 0; off >>= 1) {
            if (nr < off) {
                float4 a = ssum[nr][ln], c2 = ssum[nr + off][ln];
                a.x += c2.x; a.y += c2.y; a.z += c2.z; a.w += c2.w;
                ssum[nr][ln] = a;
                float4 m = smax[nr][ln], c3 = smax[nr + off][ln];
                m.x = fmaxf(m.x, c3.x); m.y = fmaxf(m.y, c3.y);
                m.z = fmaxf(m.z, c3.z); m.w = fmaxf(m.w, c3.w);
                smax[nr][ln] = m;
            }
            __syncthreads();
        }
        if (nr == 0) {
            float4 s = ssum[0][ln];
            float4 m = smax[0][ln];
            float* gs = &g_gsum[gfirst * 64 + ln * 4];
            unsigned int* gm = (unsigned int*)&g_gmax[gfirst * 64 + ln * 4];
            atomicAdd(gs + 0, s.x); atomicAdd(gs + 1, s.y);
            atomicAdd(gs + 2, s.z); atomicAdd(gs + 3, s.w);
            atomicMax(gm + 0, __float_as_uint(m.x));
            atomicMax(gm + 1, __float_as_uint(m.y));
            atomicMax(gm + 2, __float_as_uint(m.z));
            atomicMax(gm + 3, __float_as_uint(m.w));
        }
    } else if (node < n) {
        int g = batch[node];
        float* gs = &g_gsum[g * 64 + ln * 4];
        unsigned int* gm = (unsigned int*)&g_gmax[g * 64 + ln * 4];
        atomicAdd(gs + 0, out.x); atomicAdd(gs + 1, out.y);
        atomicAdd(gs + 2, out.z); atomicAdd(gs + 3, out.w);
        atomicMax(gm + 0, __float_as_uint(out.x));
        atomicMax(gm + 1, __float_as_uint(out.y));
        atomicMax(gm + 2, __float_as_uint(out.z));
        atomicMax(gm + 3, __float_as_uint(out.w));
    }
}

// ---- accumulate per-layer pooled features into graph output; reset pool buffers ----
__global__ void k_graphacc(float* __restrict__ out_graph) {
    int i = blockIdx.x * blockDim.x + threadIdx.x;
    if (i >= GMAX * 64) return;
    int g = i >> 6, j = i & 63;
    out_graph[g * 128 + j] += g_gmax[i];
    out_graph[g * 128 + 64 + j] += g_gsum[i] / g_cnt[g];
    g_gmax[i] = 0.0f;
    g_gsum[i] = 0.0f;
}

extern "C" void kernel_launch(void* const* d_in, const int* in_sizes, int n_in,
                              void* d_out, int out_size) {
    const float* x = (const float*)d_in[0];
    const int* ei = (const int*)d_in[1];
    const int* batch = (const int*)d_in[2];
    const float* Ws[3] = {(const float*)d_in[3], (const float*)d_in[5], (const float*)d_in[7]};
    const float* bs[3] = {(const float*)d_in[4], (const float*)d_in[6], (const float*)d_in[8]};

    int n = in_sizes[2];
    int e = in_sizes[1] / 2;

    float* out = (float*)d_out;
    float* out_nodes = out;
    float* out_graph = out + (size_t)n * 64;

    float *buf0, *buf1;
    cudaGetSymbolAddress((void**)&buf0, g_buf04);
    cudaGetSymbolAddress((void**)&buf1, g_buf14);

    int nb = (n + 511) / 512;   // scan blocks (<=256)

    k_init<<<(n + 255) / 256, 256>>>(out_graph, n);
    k_deg<<<(e + 255) / 256, 256>>>(ei, e);
    k_dis<<<(n + 255) / 256, 256>>>(batch, n);
    k_scan1<<<nb, 512>>>(n);
    k_scan2<<<1, 256>>>(nb);
    k_scan3<<<(n + 255) / 256, 256>>>(n);
    k_fill<<<(e + 255) / 256, 256>>>(ei, e);

    const float* xin = x;
    float* xouts[3] = {buf0, buf1, out_nodes};
    for (int l = 0; l < 3; l++) {
        k_gemm<<<(n + 127) / 128, 128>>>(xin, Ws[l], n);
        k_gather<<<(n + 15) / 16, 256>>>(bs[l], batch, xouts[l], n);
        k_graphacc<<<16, 256>>>(out_graph);
        xin = xouts[l];
    }
}

// round 15
// speedup vs baseline: 1.0765x; 1.0765x over previous
#include <cuda_runtime.h>

#define D 64
#define GMAX 64
#define NMAX 100000
#define EMAX 1250000

// ---- scratch (device globals). float4 => 16B alignment. ----
__device__ float4 g_h4[NMAX * D / 4];     // h' = (x @ W) * dis[row]
__device__ float4 g_buf04[NMAX * D / 4];  // layer ping-pong
__device__ float4 g_buf14[NMAX * D / 4];
__device__ int   g_degE[NMAX];            // real in-degree (no self loop)
__device__ int   g_start[NMAX];           // CSR exclusive offsets
__device__ int   g_cursor[NMAX];          // fill cursors
__device__ int   g_csr[EMAX];             // src ids grouped by dst
__device__ int   g_bsum[256];             // scan block sums
__device__ int   g_boff[256];             // scan block offsets
__device__ float g_dis[NMAX];
__device__ float g_cnt[GMAX];
__device__ float g_gmax[GMAX * D];
__device__ float g_gsum[GMAX * D];

#define g_h ((float*)g_h4)

// ---- init ----
__global__ void k_init(float* __restrict__ out_graph, int n) {
    int i = blockIdx.x * blockDim.x + threadIdx.x;
    if (i < n) g_degE[i] = 0;
    if (i < GMAX) g_cnt[i] = 0.0f;
    if (i < GMAX * D) { g_gmax[i] = 0.0f; g_gsum[i] = 0.0f; }
    if (i < GMAX * 2 * D) out_graph[i] = 0.0f;
}

// ---- in-degree over destinations; 2 edges/thread for MLP ----
__global__ void k_deg(const int* __restrict__ ei, int e) {
    int i = (blockIdx.x * blockDim.x + threadIdx.x) * 2;
    if (i + 1 < e) {
        int d0 = ei[e + i];
        int d1 = ei[e + i + 1];
        atomicAdd(&g_degE[d0], 1);
        atomicAdd(&g_degE[d1], 1);
    } else if (i < e) {
        atomicAdd(&g_degE[ei[e + i]], 1);
    }
}

// ---- scan level 1 + fused dis/cnt (dis only needs degE; cnt only needs batch) ----
__global__ void k_scan1(const int* __restrict__ batch, int n) {
    __shared__ int s[512];
    int i = blockIdx.x * 512 + threadIdx.x;
    int v = (i < n) ? g_degE[i] : 0;
    s[threadIdx.x] = v;
    if (i < n) {
        g_dis[i] = rsqrtf((float)(v + 1));
        atomicAdd(&g_cnt[batch[i]], 1.0f);
    }
    __syncthreads();
    for (int off = 1; off < 512; off <<= 1) {
        int t = (threadIdx.x >= off) ? s[threadIdx.x - off] : 0;
        __syncthreads();
        s[threadIdx.x] += t;
        __syncthreads();
    }
    if (i < n) g_start[i] = s[threadIdx.x] - v;   // exclusive
    if (threadIdx.x == 511) g_bsum[blockIdx.x] = s[511];
}
__global__ void k_scan2(int nb) {
    __shared__ int s[256];
    int v = (threadIdx.x < nb) ? g_bsum[threadIdx.x] : 0;
    s[threadIdx.x] = v;
    __syncthreads();
    for (int off = 1; off < 256; off <<= 1) {
        int t = (threadIdx.x >= off) ? s[threadIdx.x - off] : 0;
        __syncthreads();
        s[threadIdx.x] += t;
        __syncthreads();
    }
    if (threadIdx.x < nb) g_boff[threadIdx.x] = s[threadIdx.x] - v;
}
__global__ void k_scan3(int n) {
    int i = blockIdx.x * blockDim.x + threadIdx.x;
    if (i < n) {
        int st = g_start[i] + g_boff[i >> 9];
        g_start[i] = st;
        g_cursor[i] = st;
    }
}

// ---- CSR fill: 2 edges/thread (src+dst loads batched before atomics) ----
__global__ void k_fill(const int* __restrict__ ei, int e) {
    int i = (blockIdx.x * blockDim.x + threadIdx.x) * 2;
    if (i + 1 < e) {
        int d0 = ei[e + i], d1 = ei[e + i + 1];
        int s0 = ei[i],     s1 = ei[i + 1];
        int p0 = atomicAdd(&g_cursor[d0], 1);
        int p1 = atomicAdd(&g_cursor[d1], 1);
        g_csr[p0] = s0;
        g_csr[p1] = s1;
    } else if (i < e) {
        int d0 = ei[e + i];
        int p0 = atomicAdd(&g_cursor[d0], 1);
        g_csr[p0] = ei[i];
    }
}

// ---- h' = (x @ W) * dis[row] ----
// EXACT R13 version (proven 358us total). 128 rows/block, 128 threads.
// Thread (r, c) computes rows r, r+32, r+64, r+96, cols {4j+c}. Per k:
// 4 xs scalar LDS + 16 ws scalar LDS -> 64 FMA. Scalar ws is FINAL
// (LDS.128 variants regressed twice: R5 +38us, R14 +7us/launch).
__global__ void k_gemm(const float* __restrict__ x, const float* __restrict__ W, int n) {
    __shared__ float xs[128 * 64];   // 32KB, rotated rows
    __shared__ float ws[64 * 64];    // 16KB -> total 48KB = limit
    int t = threadIdx.x;             // 0..127
    int R0 = blockIdx.x * 128;
    int rows = min(128, n - R0);

    for (int i = t; i < 64 * 16; i += 128)
        ((float4*)ws)[i] = ((const float4*)W)[i];
    for (int i = t; i < rows * 16; i += 128) {
        int rr = i >> 4, c4 = i & 15;
        int roff = ((c4 * 4 + rr * 4) & 63);          // rotated, 16B-aligned
        *(float4*)(xs + rr * 64 + roff) = *((const float4*)(x + (size_t)(R0 + rr) * 64) + c4);
    }
    __syncthreads();

    int r = t >> 2;      // 0..31 -> rows r, r+32, r+64, r+96
    int c = t & 3;       // 0..3  -> cols 4j+c
    int rot = (r * 4) & 63;
    const float* x0 = xs + r * 64;
    const float* x1 = xs + (r + 32) * 64;
    const float* x2 = xs + (r + 64) * 64;
    const float* x3 = xs + (r + 96) * 64;

    float acc0[16], acc1[16], acc2[16], acc3[16];
#pragma unroll
    for (int j = 0; j < 16; j++) { acc0[j] = 0.f; acc1[j] = 0.f; acc2[j] = 0.f; acc3[j] = 0.f; }
#pragma unroll 16
    for (int k = 0; k < 64; k++) {
        int koff = (k + rot) & 63;
        float xv0 = x0[koff];
        float xv1 = x1[koff];
        float xv2 = x2[koff];
        float xv3 = x3[koff];
        const float* wrow = ws + k * 64;
#pragma unroll
        for (int j = 0; j < 16; j++) {
            float w = wrow[4 * j + c];
            acc0[j] += xv0 * w;
            acc1[j] += xv1 * w;
            acc2[j] += xv2 * w;
            acc3[j] += xv3 * w;
        }
    }
#pragma unroll
    for (int q = 0; q < 4; q++) {
        int gr = R0 + r + q * 32;
        if (r + q * 32 < rows) {
            float s = g_dis[gr];
            float* hp = g_h + (size_t)gr * 64;
            const float* a = (q == 0) ? acc0 : (q == 1) ? acc1 : (q == 2) ? acc2 : acc3;
#pragma unroll
            for (int j = 0; j < 16; j++) hp[4 * j + c] = a[j] * s;
        }
    }
}

// ---- fused gather + epilogue + pooling ----
// EXACT R12/R13 version (proven). 16 nodes/block x 16 threads/node.
__global__ void k_gather(const float* __restrict__ b, const int* __restrict__ batch,
                         float* __restrict__ xout, int n) {
    int t = threadIdx.x;
    int ln = t & 15;          // float4 lane (cols 4*ln .. 4*ln+3)
    int nr = t >> 4;          // node-in-block 0..15
    int node = blockIdx.x * 16 + nr;

    float4 acc = {0.f, 0.f, 0.f, 0.f};
    float4 out = {0.f, 0.f, 0.f, 0.f};
    if (node < n) {
        acc = g_h4[(size_t)node * 16 + ln];           // self loop (already *dis[node])
        float4 accB = {0.f, 0.f, 0.f, 0.f};
        int st = g_start[node];
        int end = st + g_degE[node];
        int k = st;
        for (; k + 3 < end; k += 4) {
            int s0 = g_csr[k],     s1 = g_csr[k + 1];
            int s2 = g_csr[k + 2], s3 = g_csr[k + 3];
            float4 v0 = g_h4[(size_t)s0 * 16 + ln];
            float4 v1 = g_h4[(size_t)s1 * 16 + ln];
            float4 v2 = g_h4[(size_t)s2 * 16 + ln];
            float4 v3 = g_h4[(size_t)s3 * 16 + ln];
            acc.x += v0.x + v1.x;  accB.x += v2.x + v3.x;
            acc.y += v0.y + v1.y;  accB.y += v2.y + v3.y;
            acc.z += v0.z + v1.z;  accB.z += v2.z + v3.z;
            acc.w += v0.w + v1.w;  accB.w += v2.w + v3.w;
        }
        for (; k < end; k++) {
            int s0 = g_csr[k];
            float4 v0 = g_h4[(size_t)s0 * 16 + ln];
            acc.x += v0.x; acc.y += v0.y; acc.z += v0.z; acc.w += v0.w;
        }
        acc.x += accB.x; acc.y += accB.y; acc.z += accB.z; acc.w += accB.w;

        float d = g_dis[node];
        float4 bb = ((const float4*)b)[ln];
        out.x = fmaxf(fmaf(d, acc.x, bb.x), 0.f);
        out.y = fmaxf(fmaf(d, acc.y, bb.y), 0.f);
        out.z = fmaxf(fmaf(d, acc.z, bb.z), 0.f);
        out.w = fmaxf(fmaf(d, acc.w, bb.w), 0.f);
        ((float4*)xout)[(size_t)node * 16 + ln] = out;
    }

    // pooling
    int R0 = blockIdx.x * 16;
    int last = min(R0 + 15, n - 1);
    int gfirst = batch[R0];
    int glast = batch[last];

    if (gfirst == glast) {
        __shared__ float4 ssum[16][16];
        __shared__ float4 smax[16][16];
        ssum[nr][ln] = out;               // out==0 for node>=n: identity for sum, safe for relu-max
        smax[nr][ln] = out;
        __syncthreads();
#pragma unroll
        for (int off = 8; off > 0; off >>= 1) {
            if (nr < off) {
                float4 a = ssum[nr][ln], c2 = ssum[nr + off][ln];
                a.x += c2.x; a.y += c2.y; a.z += c2.z; a.w += c2.w;
                ssum[nr][ln] = a;
                float4 m = smax[nr][ln], c3 = smax[nr + off][ln];
                m.x = fmaxf(m.x, c3.x); m.y = fmaxf(m.y, c3.y);
                m.z = fmaxf(m.z, c3.z); m.w = fmaxf(m.w, c3.w);
                smax[nr][ln] = m;
            }
            __syncthreads();
        }
        if (nr == 0) {
            float4 s = ssum[0][ln];
            float4 m = smax[0][ln];
            float* gs = &g_gsum[gfirst * 64 + ln * 4];
            unsigned int* gm = (unsigned int*)&g_gmax[gfirst * 64 + ln * 4];
            atomicAdd(gs + 0, s.x); atomicAdd(gs + 1, s.y);
            atomicAdd(gs + 2, s.z); atomicAdd(gs + 3, s.w);
            atomicMax(gm + 0, __float_as_uint(m.x));
            atomicMax(gm + 1, __float_as_uint(m.y));
            atomicMax(gm + 2, __float_as_uint(m.z));
            atomicMax(gm + 3, __float_as_uint(m.w));
        }
    } else if (node < n) {
        int g = batch[node];
        float* gs = &g_gsum[g * 64 + ln * 4];
        unsigned int* gm = (unsigned int*)&g_gmax[g * 64 + ln * 4];
        atomicAdd(gs + 0, out.x); atomicAdd(gs + 1, out.y);
        atomicAdd(gs + 2, out.z); atomicAdd(gs + 3, out.w);
        atomicMax(gm + 0, __float_as_uint(out.x));
        atomicMax(gm + 1, __float_as_uint(out.y));
        atomicMax(gm + 2, __float_as_uint(out.z));
        atomicMax(gm + 3, __float_as_uint(out.w));
    }
}

// ---- accumulate per-layer pooled features into graph output; reset pool buffers ----
__global__ void k_graphacc(float* __restrict__ out_graph) {
    int i = blockIdx.x * blockDim.x + threadIdx.x;
    if (i >= GMAX * 64) return;
    int g = i >> 6, j = i & 63;
    out_graph[g * 128 + j] += g_gmax[i];
    out_graph[g * 128 + 64 + j] += g_gsum[i] / g_cnt[g];
    g_gmax[i] = 0.0f;
    g_gsum[i] = 0.0f;
}

extern "C" void kernel_launch(void* const* d_in, const int* in_sizes, int n_in,
                              void* d_out, int out_size) {
    const float* x = (const float*)d_in[0];
    const int* ei = (const int*)d_in[1];
    const int* batch = (const int*)d_in[2];
    const float* Ws[3] = {(const float*)d_in[3], (const float*)d_in[5], (const float*)d_in[7]};
    const float* bs[3] = {(const float*)d_in[4], (const float*)d_in[6], (const float*)d_in[8]};

    int n = in_sizes[2];
    int e = in_sizes[1] / 2;

    float* out = (float*)d_out;
    float* out_nodes = out;
    float* out_graph = out + (size_t)n * 64;

    float *buf0, *buf1;
    cudaGetSymbolAddress((void**)&buf0, g_buf04);
    cudaGetSymbolAddress((void**)&buf1, g_buf14);

    int nb = (n + 511) / 512;   // scan blocks (<=256)

    k_init<<<(n + 255) / 256, 256>>>(out_graph, n);
    k_deg<<<(e / 2 + 255) / 256, 256>>>(ei, e);
    k_scan1<<<nb, 512>>>(batch, n);
    k_scan2<<<1, 256>>>(nb);
    k_scan3<<<(n + 255) / 256, 256>>>(n);
    k_fill<<<(e / 2 + 255) / 256, 256>>>(ei, e);

    const float* xin = x;
    float* xouts[3] = {buf0, buf1, out_nodes};
    for (int l = 0; l < 3; l++) {
        k_gemm<<<(n + 127) / 128, 128>>>(xin, Ws[l], n);
        k_gather<<<(n + 15) / 16, 256>>>(bs[l], batch, xouts[l], n);
        k_graphacc<<<16, 256>>>(out_graph);
        xin = xouts[l];
    }
}

// round 16
// speedup vs baseline: 1.0881x; 1.0107x over previous
#include <cuda_runtime.h>

#define D 64
#define GMAX 64
#define NMAX 100000
#define EMAX 1250000

// ---- scratch (device globals). float4 => 16B alignment. ----
__device__ float4 g_h4[NMAX * D / 4];     // h' = (x @ W) * dis[row]
__device__ float4 g_buf04[NMAX * D / 4];  // layer ping-pong
__device__ float4 g_buf14[NMAX * D / 4];
__device__ int   g_degE[NMAX];            // real in-degree (no self loop)
__device__ int   g_start[NMAX];           // CSR exclusive offsets
__device__ int   g_cursor[NMAX];          // fill cursors
__device__ int   g_csr[EMAX];             // src ids grouped by dst
__device__ int   g_bsum[256];             // scan block sums
__device__ int   g_boff[256];             // scan block offsets
__device__ float g_dis[NMAX];
__device__ float g_cnt[GMAX];
__device__ float g_gmax[GMAX * D];
__device__ float g_gsum[GMAX * D];

#define g_h ((float*)g_h4)

// ---- init ----
__global__ void k_init(float* __restrict__ out_graph, int n) {
    int i = blockIdx.x * blockDim.x + threadIdx.x;
    if (i < n) g_degE[i] = 0;
    if (i < GMAX) g_cnt[i] = 0.0f;
    if (i < GMAX * D) { g_gmax[i] = 0.0f; g_gsum[i] = 0.0f; }
    if (i < GMAX * 2 * D) out_graph[i] = 0.0f;
}

// ---- in-degree over destinations; 2 edges/thread for MLP ----
__global__ void k_deg(const int* __restrict__ ei, int e) {
    int i = (blockIdx.x * blockDim.x + threadIdx.x) * 2;
    if (i + 1 < e) {
        int d0 = ei[e + i];
        int d1 = ei[e + i + 1];
        atomicAdd(&g_degE[d0], 1);
        atomicAdd(&g_degE[d1], 1);
    } else if (i < e) {
        atomicAdd(&g_degE[ei[e + i]], 1);
    }
}

// ---- scan level 1 + fused dis/cnt ----
__global__ void k_scan1(const int* __restrict__ batch, int n) {
    __shared__ int s[512];
    int i = blockIdx.x * 512 + threadIdx.x;
    int v = (i < n) ? g_degE[i] : 0;
    s[threadIdx.x] = v;
    if (i < n) {
        g_dis[i] = rsqrtf((float)(v + 1));
        atomicAdd(&g_cnt[batch[i]], 1.0f);
    }
    __syncthreads();
    for (int off = 1; off < 512; off <<= 1) {
        int t = (threadIdx.x >= off) ? s[threadIdx.x - off] : 0;
        __syncthreads();
        s[threadIdx.x] += t;
        __syncthreads();
    }
    if (i < n) g_start[i] = s[threadIdx.x] - v;   // exclusive
    if (threadIdx.x == 511) g_bsum[blockIdx.x] = s[511];
}
__global__ void k_scan2(int nb) {
    __shared__ int s[256];
    int v = (threadIdx.x < nb) ? g_bsum[threadIdx.x] : 0;
    s[threadIdx.x] = v;
    __syncthreads();
    for (int off = 1; off < 256; off <<= 1) {
        int t = (threadIdx.x >= off) ? s[threadIdx.x - off] : 0;
        __syncthreads();
        s[threadIdx.x] += t;
        __syncthreads();
    }
    if (threadIdx.x < nb) g_boff[threadIdx.x] = s[threadIdx.x] - v;
}
__global__ void k_scan3(int n) {
    int i = blockIdx.x * blockDim.x + threadIdx.x;
    if (i < n) {
        int st = g_start[i] + g_boff[i >> 9];
        g_start[i] = st;
        g_cursor[i] = st;
    }
}

// ---- CSR fill: 2 edges/thread ----
__global__ void k_fill(const int* __restrict__ ei, int e) {
    int i = (blockIdx.x * blockDim.x + threadIdx.x) * 2;
    if (i + 1 < e) {
        int d0 = ei[e + i], d1 = ei[e + i + 1];
        int s0 = ei[i],     s1 = ei[i + 1];
        int p0 = atomicAdd(&g_cursor[d0], 1);
        int p1 = atomicAdd(&g_cursor[d1], 1);
        g_csr[p0] = s0;
        g_csr[p1] = s1;
    } else if (i < e) {
        int d0 = ei[e + i];
        int p0 = atomicAdd(&g_cursor[d0], 1);
        g_csr[p0] = ei[i];
    }
}

// ---- h' = (x @ W) * dis[row] ----
// 128 rows/block, 128 threads, 4 rows/thread, scalar ws (proven).
// NEW: smem-staged epilogue — accumulators go to rotated xs via conflict-free
// STS, then read back as float4 and stored with coalesced STG.128
// (replaces 64 scattered STG.32/thread that cost ~8 L1 wavefronts each).
__global__ void k_gemm(const float* __restrict__ x, const float* __restrict__ W, int n) {
    __shared__ float xs[128 * 64];   // 32KB, rotated rows (input, then output staging)
    __shared__ float ws[64 * 64];    // 16KB -> total 48KB = limit
    int t = threadIdx.x;             // 0..127
    int R0 = blockIdx.x * 128;
    int rows = min(128, n - R0);

    for (int i = t; i < 64 * 16; i += 128)
        ((float4*)ws)[i] = ((const float4*)W)[i];
    for (int i = t; i < rows * 16; i += 128) {
        int rr = i >> 4, c4 = i & 15;
        int roff = ((c4 * 4 + rr * 4) & 63);          // rotated, 16B-aligned
        *(float4*)(xs + rr * 64 + roff) = *((const float4*)(x + (size_t)(R0 + rr) * 64) + c4);
    }
    __syncthreads();

    int r = t >> 2;      // 0..31 -> rows r, r+32, r+64, r+96
    int c = t & 3;       // 0..3  -> cols 4j+c
    int rot = (r * 4) & 63;
    const float* x0 = xs + r * 64;
    const float* x1 = xs + (r + 32) * 64;
    const float* x2 = xs + (r + 64) * 64;
    const float* x3 = xs + (r + 96) * 64;

    float acc0[16], acc1[16], acc2[16], acc3[16];
#pragma unroll
    for (int j = 0; j < 16; j++) { acc0[j] = 0.f; acc1[j] = 0.f; acc2[j] = 0.f; acc3[j] = 0.f; }
#pragma unroll 16
    for (int k = 0; k < 64; k++) {
        int koff = (k + rot) & 63;
        float xv0 = x0[koff];
        float xv1 = x1[koff];
        float xv2 = x2[koff];
        float xv3 = x3[koff];
        const float* wrow = ws + k * 64;
#pragma unroll
        for (int j = 0; j < 16; j++) {
            float w = wrow[4 * j + c];
            acc0[j] += xv0 * w;
            acc1[j] += xv1 * w;
            acc2[j] += xv2 * w;
            acc3[j] += xv3 * w;
        }
    }

    // ---- staged epilogue: acc -> rotated xs (STS, conflict-free) ----
    __syncthreads();   // everyone done reading xs
#pragma unroll
    for (int q = 0; q < 4; q++) {
        int rr = r + q * 32;
        int gr = R0 + rr;
        float s = (rr < rows) ? g_dis[gr] : 0.f;
        float* xrow = xs + rr * 64;
        const float* a = (q == 0) ? acc0 : (q == 1) ? acc1 : (q == 2) ? acc2 : acc3;
#pragma unroll
        for (int j = 0; j < 16; j++) {
            // rotation identical to the load layout: offset (col + 4*rr)&63 == (col + rot)&63
            xrow[(4 * j + c + rot) & 63] = a[j] * s;
        }
    }
    __syncthreads();

    // ---- coalesced readout: rotated xs -> g_h as float4 (STG.128) ----
    for (int i = t; i < rows * 16; i += 128) {
        int rr = i >> 4, c4 = i & 15;
        int roff = ((c4 * 4 + rr * 4) & 63);
        float4 v = *(const float4*)(xs + rr * 64 + roff);
        *((float4*)(g_h + (size_t)(R0 + rr) * 64) + c4) = v;
    }
}

// ---- fused gather + epilogue + pooling ----
// EXACT R12/R13 version (proven). 16 nodes/block x 16 threads/node.
__global__ void k_gather(const float* __restrict__ b, const int* __restrict__ batch,
                         float* __restrict__ xout, int n) {
    int t = threadIdx.x;
    int ln = t & 15;          // float4 lane (cols 4*ln .. 4*ln+3)
    int nr = t >> 4;          // node-in-block 0..15
    int node = blockIdx.x * 16 + nr;

    float4 acc = {0.f, 0.f, 0.f, 0.f};
    float4 out = {0.f, 0.f, 0.f, 0.f};
    if (node < n) {
        acc = g_h4[(size_t)node * 16 + ln];           // self loop (already *dis[node])
        float4 accB = {0.f, 0.f, 0.f, 0.f};
        int st = g_start[node];
        int end = st + g_degE[node];
        int k = st;
        for (; k + 3 < end; k += 4) {
            int s0 = g_csr[k],     s1 = g_csr[k + 1];
            int s2 = g_csr[k + 2], s3 = g_csr[k + 3];
            float4 v0 = g_h4[(size_t)s0 * 16 + ln];
            float4 v1 = g_h4[(size_t)s1 * 16 + ln];
            float4 v2 = g_h4[(size_t)s2 * 16 + ln];
            float4 v3 = g_h4[(size_t)s3 * 16 + ln];
            acc.x += v0.x + v1.x;  accB.x += v2.x + v3.x;
            acc.y += v0.y + v1.y;  accB.y += v2.y + v3.y;
            acc.z += v0.z + v1.z;  accB.z += v2.z + v3.z;
            acc.w += v0.w + v1.w;  accB.w += v2.w + v3.w;
        }
        for (; k < end; k++) {
            int s0 = g_csr[k];
            float4 v0 = g_h4[(size_t)s0 * 16 + ln];
            acc.x += v0.x; acc.y += v0.y; acc.z += v0.z; acc.w += v0.w;
        }
        acc.x += accB.x; acc.y += accB.y; acc.z += accB.z; acc.w += accB.w;

        float d = g_dis[node];
        float4 bb = ((const float4*)b)[ln];
        out.x = fmaxf(fmaf(d, acc.x, bb.x), 0.f);
        out.y = fmaxf(fmaf(d, acc.y, bb.y), 0.f);
        out.z = fmaxf(fmaf(d, acc.z, bb.z), 0.f);
        out.w = fmaxf(fmaf(d, acc.w, bb.w), 0.f);
        ((float4*)xout)[(size_t)node * 16 + ln] = out;
    }

    // pooling
    int R0 = blockIdx.x * 16;
    int last = min(R0 + 15, n - 1);
    int gfirst = batch[R0];
    int glast = batch[last];

    if (gfirst == glast) {
        __shared__ float4 ssum[16][16];
        __shared__ float4 smax[16][16];
        ssum[nr][ln] = out;               // out==0 for node>=n: identity for sum, safe for relu-max
        smax[nr][ln] = out;
        __syncthreads();
#pragma unroll
        for (int off = 8; off > 0; off >>= 1) {
            if (nr < off) {
                float4 a = ssum[nr][ln], c2 = ssum[nr + off][ln];
                a.x += c2.x; a.y += c2.y; a.z += c2.z; a.w += c2.w;
                ssum[nr][ln] = a;
                float4 m = smax[nr][ln], c3 = smax[nr + off][ln];
                m.x = fmaxf(m.x, c3.x); m.y = fmaxf(m.y, c3.y);
                m.z = fmaxf(m.z, c3.z); m.w = fmaxf(m.w, c3.w);
                smax[nr][ln] = m;
            }
            __syncthreads();
        }
        if (nr == 0) {
            float4 s = ssum[0][ln];
            float4 m = smax[0][ln];
            float* gs = &g_gsum[gfirst * 64 + ln * 4];
            unsigned int* gm = (unsigned int*)&g_gmax[gfirst * 64 + ln * 4];
            atomicAdd(gs + 0, s.x); atomicAdd(gs + 1, s.y);
            atomicAdd(gs + 2, s.z); atomicAdd(gs + 3, s.w);
            atomicMax(gm + 0, __float_as_uint(m.x));
            atomicMax(gm + 1, __float_as_uint(m.y));
            atomicMax(gm + 2, __float_as_uint(m.z));
            atomicMax(gm + 3, __float_as_uint(m.w));
        }
    } else if (node < n) {
        int g = batch[node];
        float* gs = &g_gsum[g * 64 + ln * 4];
        unsigned int* gm = (unsigned int*)&g_gmax[g * 64 + ln * 4];
        atomicAdd(gs + 0, out.x); atomicAdd(gs + 1, out.y);
        atomicAdd(gs + 2, out.z); atomicAdd(gs + 3, out.w);
        atomicMax(gm + 0, __float_as_uint(out.x));
        atomicMax(gm + 1, __float_as_uint(out.y));
        atomicMax(gm + 2, __float_as_uint(out.z));
        atomicMax(gm + 3, __float_as_uint(out.w));
    }
}

// ---- accumulate per-layer pooled features into graph output; reset pool buffers ----
__global__ void k_graphacc(float* __restrict__ out_graph) {
    int i = blockIdx.x * blockDim.x + threadIdx.x;
    if (i >= GMAX * 64) return;
    int g = i >> 6, j = i & 63;
    out_graph[g * 128 + j] += g_gmax[i];
    out_graph[g * 128 + 64 + j] += g_gsum[i] / g_cnt[g];
    g_gmax[i] = 0.0f;
    g_gsum[i] = 0.0f;
}

extern "C" void kernel_launch(void* const* d_in, const int* in_sizes, int n_in,
                              void* d_out, int out_size) {
    const float* x = (const float*)d_in[0];
    const int* ei = (const int*)d_in[1];
    const int* batch = (const int*)d_in[2];
    const float* Ws[3] = {(const float*)d_in[3], (const float*)d_in[5], (const float*)d_in[7]};
    const float* bs[3] = {(const float*)d_in[4], (const float*)d_in[6], (const float*)d_in[8]};

    int n = in_sizes[2];
    int e = in_sizes[1] / 2;

    float* out = (float*)d_out;
    float* out_nodes = out;
    float* out_graph = out + (size_t)n * 64;

    float *buf0, *buf1;
    cudaGetSymbolAddress((void**)&buf0, g_buf04);
    cudaGetSymbolAddress((void**)&buf1, g_buf14);

    int nb = (n + 511) / 512;   // scan blocks (<=256)

    k_init<<<(n + 255) / 256, 256>>>(out_graph, n);
    k_deg<<<(e / 2 + 255) / 256, 256>>>(ei, e);
    k_scan1<<<nb, 512>>>(batch, n);
    k_scan2<<<1, 256>>>(nb);
    k_scan3<<<(n + 255) / 256, 256>>>(n);
    k_fill<<<(e / 2 + 255) / 256, 256>>>(ei, e);

    const float* xin = x;
    float* xouts[3] = {buf0, buf1, out_nodes};
    for (int l = 0; l < 3; l++) {
        k_gemm<<<(n + 127) / 128, 128>>>(xin, Ws[l], n);
        k_gather<<<(n + 15) / 16, 256>>>(bs[l], batch, xouts[l], n);
        k_graphacc<<<16, 256>>>(out_graph);
        xin = xouts[l];
    }
}

// round 17
// speedup vs baseline: 1.1083x; 1.0186x over previous
#include <cuda_runtime.h>

#define D 64
#define GMAX 64
#define NMAX 100000
#define EMAX 1250000

// ---- scratch (device globals). float4 => 16B alignment. ----
__device__ float4 g_h4[NMAX * D / 4];     // h' = (x @ W) * dis[row]
__device__ float4 g_buf04[NMAX * D / 4];  // layer ping-pong
__device__ float4 g_buf14[NMAX * D / 4];
__device__ int   g_degE[NMAX];            // real in-degree (no self loop)
__device__ int   g_start[NMAX];           // CSR exclusive offsets
__device__ int   g_cursor[NMAX];          // fill cursors
__device__ int   g_csr[EMAX];             // src ids grouped by dst
__device__ int   g_bsum[256];             // scan block sums
__device__ int   g_boff[256];             // scan block offsets
__device__ float g_dis[NMAX];
__device__ float g_cnt[GMAX];
__device__ float g_gmax[GMAX * D];
__device__ float g_gsum[GMAX * D];

#define g_h ((float*)g_h4)

// ---- init ----
__global__ void k_init(float* __restrict__ out_graph, int n) {
    int i = blockIdx.x * blockDim.x + threadIdx.x;
    if (i < n) g_degE[i] = 0;
    if (i < GMAX) g_cnt[i] = 0.0f;
    if (i < GMAX * D) { g_gmax[i] = 0.0f; g_gsum[i] = 0.0f; }
    if (i < GMAX * 2 * D) out_graph[i] = 0.0f;
}

// ---- in-degree over destinations; 2 edges/thread for MLP ----
__global__ void k_deg(const int* __restrict__ ei, int e) {
    int i = (blockIdx.x * blockDim.x + threadIdx.x) * 2;
    if (i + 1 < e) {
        int d0 = ei[e + i];
        int d1 = ei[e + i + 1];
        atomicAdd(&g_degE[d0], 1);
        atomicAdd(&g_degE[d1], 1);
    } else if (i < e) {
        atomicAdd(&g_degE[ei[e + i]], 1);
    }
}

// ---- scan level 1 + fused dis/cnt ----
__global__ void k_scan1(const int* __restrict__ batch, int n) {
    __shared__ int s[512];
    int i = blockIdx.x * 512 + threadIdx.x;
    int v = (i < n) ? g_degE[i] : 0;
    s[threadIdx.x] = v;
    if (i < n) {
        g_dis[i] = rsqrtf((float)(v + 1));
        atomicAdd(&g_cnt[batch[i]], 1.0f);
    }
    __syncthreads();
    for (int off = 1; off < 512; off <<= 1) {
        int t = (threadIdx.x >= off) ? s[threadIdx.x - off] : 0;
        __syncthreads();
        s[threadIdx.x] += t;
        __syncthreads();
    }
    if (i < n) g_start[i] = s[threadIdx.x] - v;   // exclusive
    if (threadIdx.x == 511) g_bsum[blockIdx.x] = s[511];
}
__global__ void k_scan2(int nb) {
    __shared__ int s[256];
    int v = (threadIdx.x < nb) ? g_bsum[threadIdx.x] : 0;
    s[threadIdx.x] = v;
    __syncthreads();
    for (int off = 1; off < 256; off <<= 1) {
        int t = (threadIdx.x >= off) ? s[threadIdx.x - off] : 0;
        __syncthreads();
        s[threadIdx.x] += t;
        __syncthreads();
    }
    if (threadIdx.x < nb) g_boff[threadIdx.x] = s[threadIdx.x] - v;
}
__global__ void k_scan3(int n) {
    int i = blockIdx.x * blockDim.x + threadIdx.x;
    if (i < n) {
        int st = g_start[i] + g_boff[i >> 9];
        g_start[i] = st;
        g_cursor[i] = st;
    }
}

// ---- CSR fill: 2 edges/thread ----
__global__ void k_fill(const int* __restrict__ ei, int e) {
    int i = (blockIdx.x * blockDim.x + threadIdx.x) * 2;
    if (i + 1 < e) {
        int d0 = ei[e + i], d1 = ei[e + i + 1];
        int s0 = ei[i],     s1 = ei[i + 1];
        int p0 = atomicAdd(&g_cursor[d0], 1);
        int p1 = atomicAdd(&g_cursor[d1], 1);
        g_csr[p0] = s0;
        g_csr[p1] = s1;
    } else if (i < e) {
        int d0 = ei[e + i];
        int p0 = atomicAdd(&g_cursor[d0], 1);
        g_csr[p0] = ei[i];
    }
}

// ---- h' = (x @ W) * dis[row] ----
// 128 rows/block, 128 threads. NEW mapping: thread (r in 0..15, c in 0..7)
// computes 8 rows {r+16m} x 8 cols {8j+c}: per k = 8 xs + 8 ws scalar LDS
// for 64 FMA (LDS/FMA 0.25, the a+b minimum for a*b=64; was 20 LDS = 0.31).
// xs: 4 distinct rows/warp, distinct banks, 8-way broadcast. ws: 8 distinct
// banks, 4-way broadcast. Rotation (4*row)&63 invariant across the 8 rows.
__global__ void k_gemm(const float* __restrict__ x, const float* __restrict__ W, int n) {
    __shared__ float xs[128 * 64];   // 32KB, rotated rows (input, then output staging)
    __shared__ float ws[64 * 64];    // 16KB -> total 48KB = limit
    int t = threadIdx.x;             // 0..127
    int R0 = blockIdx.x * 128;
    int rows = min(128, n - R0);

    for (int i = t; i < 64 * 16; i += 128)
        ((float4*)ws)[i] = ((const float4*)W)[i];
    for (int i = t; i < rows * 16; i += 128) {
        int rr = i >> 4, c4 = i & 15;
        int roff = ((c4 * 4 + rr * 4) & 63);          // rotated, 16B-aligned
        *(float4*)(xs + rr * 64 + roff) = *((const float4*)(x + (size_t)(R0 + rr) * 64) + c4);
    }
    __syncthreads();

    int r = t >> 3;      // 0..15 -> rows r, r+16, ..., r+112
    int c = t & 7;       // 0..7  -> cols 8j+c
    int rot = (r * 4) & 63;

    float acc[8][8];     // [row m][col j]
#pragma unroll
    for (int m = 0; m < 8; m++)
#pragma unroll
        for (int j = 0; j < 8; j++) acc[m][j] = 0.f;

#pragma unroll 8
    for (int k = 0; k < 64; k++) {
        int koff = (k + rot) & 63;
        float xv[8];
#pragma unroll
        for (int m = 0; m < 8; m++) xv[m] = xs[(r + 16 * m) * 64 + koff];
        const float* wrow = ws + k * 64;
        float wv[8];
#pragma unroll
        for (int j = 0; j < 8; j++) wv[j] = wrow[8 * j + c];
#pragma unroll
        for (int m = 0; m < 8; m++)
#pragma unroll
            for (int j = 0; j < 8; j++) acc[m][j] += xv[m] * wv[j];
    }

    // ---- staged epilogue: acc -> rotated xs (STS), then coalesced STG.128 ----
    __syncthreads();   // everyone done reading xs
#pragma unroll
    for (int m = 0; m < 8; m++) {
        int rr = r + 16 * m;
        int gr = R0 + rr;
        float s = (rr < rows) ? g_dis[gr] : 0.f;
        float* xrow = xs + rr * 64;
#pragma unroll
        for (int j = 0; j < 8; j++) {
            xrow[(8 * j + c + rot) & 63] = acc[m][j] * s;
        }
    }
    __syncthreads();

    for (int i = t; i < rows * 16; i += 128) {
        int rr = i >> 4, c4 = i & 15;
        int roff = ((c4 * 4 + rr * 4) & 63);
        float4 v = *(const float4*)(xs + rr * 64 + roff);
        *((float4*)(g_h + (size_t)(R0 + rr) * 64) + c4) = v;
    }
}

// ---- fused gather + epilogue + pooling ----
// EXACT R12/R13 version (proven). 16 nodes/block x 16 threads/node.
__global__ void k_gather(const float* __restrict__ b, const int* __restrict__ batch,
                         float* __restrict__ xout, int n) {
    int t = threadIdx.x;
    int ln = t & 15;          // float4 lane (cols 4*ln .. 4*ln+3)
    int nr = t >> 4;          // node-in-block 0..15
    int node = blockIdx.x * 16 + nr;

    float4 acc = {0.f, 0.f, 0.f, 0.f};
    float4 out = {0.f, 0.f, 0.f, 0.f};
    if (node < n) {
        acc = g_h4[(size_t)node * 16 + ln];           // self loop (already *dis[node])
        float4 accB = {0.f, 0.f, 0.f, 0.f};
        int st = g_start[node];
        int end = st + g_degE[node];
        int k = st;
        for (; k + 3 < end; k += 4) {
            int s0 = g_csr[k],     s1 = g_csr[k + 1];
            int s2 = g_csr[k + 2], s3 = g_csr[k + 3];
            float4 v0 = g_h4[(size_t)s0 * 16 + ln];
            float4 v1 = g_h4[(size_t)s1 * 16 + ln];
            float4 v2 = g_h4[(size_t)s2 * 16 + ln];
            float4 v3 = g_h4[(size_t)s3 * 16 + ln];
            acc.x += v0.x + v1.x;  accB.x += v2.x + v3.x;
            acc.y += v0.y + v1.y;  accB.y += v2.y + v3.y;
            acc.z += v0.z + v1.z;  accB.z += v2.z + v3.z;
            acc.w += v0.w + v1.w;  accB.w += v2.w + v3.w;
        }
        for (; k < end; k++) {
            int s0 = g_csr[k];
            float4 v0 = g_h4[(size_t)s0 * 16 + ln];
            acc.x += v0.x; acc.y += v0.y; acc.z += v0.z; acc.w += v0.w;
        }
        acc.x += accB.x; acc.y += accB.y; acc.z += accB.z; acc.w += accB.w;

        float d = g_dis[node];
        float4 bb = ((const float4*)b)[ln];
        out.x = fmaxf(fmaf(d, acc.x, bb.x), 0.f);
        out.y = fmaxf(fmaf(d, acc.y, bb.y), 0.f);
        out.z = fmaxf(fmaf(d, acc.z, bb.z), 0.f);
        out.w = fmaxf(fmaf(d, acc.w, bb.w), 0.f);
        ((float4*)xout)[(size_t)node * 16 + ln] = out;
    }

    // pooling
    int R0 = blockIdx.x * 16;
    int last = min(R0 + 15, n - 1);
    int gfirst = batch[R0];
    int glast = batch[last];

    if (gfirst == glast) {
        __shared__ float4 ssum[16][16];
        __shared__ float4 smax[16][16];
        ssum[nr][ln] = out;               // out==0 for node>=n: identity for sum, safe for relu-max
        smax[nr][ln] = out;
        __syncthreads();
#pragma unroll
        for (int off = 8; off > 0; off >>= 1) {
            if (nr < off) {
                float4 a = ssum[nr][ln], c2 = ssum[nr + off][ln];
                a.x += c2.x; a.y += c2.y; a.z += c2.z; a.w += c2.w;
                ssum[nr][ln] = a;
                float4 m = smax[nr][ln], c3 = smax[nr + off][ln];
                m.x = fmaxf(m.x, c3.x); m.y = fmaxf(m.y, c3.y);
                m.z = fmaxf(m.z, c3.z); m.w = fmaxf(m.w, c3.w);
                smax[nr][ln] = m;
            }
            __syncthreads();
        }
        if (nr == 0) {
            float4 s = ssum[0][ln];
            float4 m = smax[0][ln];
            float* gs = &g_gsum[gfirst * 64 + ln * 4];
            unsigned int* gm = (unsigned int*)&g_gmax[gfirst * 64 + ln * 4];
            atomicAdd(gs + 0, s.x); atomicAdd(gs + 1, s.y);
            atomicAdd(gs + 2, s.z); atomicAdd(gs + 3, s.w);
            atomicMax(gm + 0, __float_as_uint(m.x));
            atomicMax(gm + 1, __float_as_uint(m.y));
            atomicMax(gm + 2, __float_as_uint(m.z));
            atomicMax(gm + 3, __float_as_uint(m.w));
        }
    } else if (node < n) {
        int g = batch[node];
        float* gs = &g_gsum[g * 64 + ln * 4];
        unsigned int* gm = (unsigned int*)&g_gmax[g * 64 + ln * 4];
        atomicAdd(gs + 0, out.x); atomicAdd(gs + 1, out.y);
        atomicAdd(gs + 2, out.z); atomicAdd(gs + 3, out.w);
        atomicMax(gm + 0, __float_as_uint(out.x));
        atomicMax(gm + 1, __float_as_uint(out.y));
        atomicMax(gm + 2, __float_as_uint(out.z));
        atomicMax(gm + 3, __float_as_uint(out.w));
    }
}

// ---- accumulate per-layer pooled features into graph output; reset pool buffers ----
__global__ void k_graphacc(float* __restrict__ out_graph) {
    int i = blockIdx.x * blockDim.x + threadIdx.x;
    if (i >= GMAX * 64) return;
    int g = i >> 6, j = i & 63;
    out_graph[g * 128 + j] += g_gmax[i];
    out_graph[g * 128 + 64 + j] += g_gsum[i] / g_cnt[g];
    g_gmax[i] = 0.0f;
    g_gsum[i] = 0.0f;
}

extern "C" void kernel_launch(void* const* d_in, const int* in_sizes, int n_in,
                              void* d_out, int out_size) {
    const float* x = (const float*)d_in[0];
    const int* ei = (const int*)d_in[1];
    const int* batch = (const int*)d_in[2];
    const float* Ws[3] = {(const float*)d_in[3], (const float*)d_in[5], (const float*)d_in[7]};
    const float* bs[3] = {(const float*)d_in[4], (const float*)d_in[6], (const float*)d_in[8]};

    int n = in_sizes[2];
    int e = in_sizes[1] / 2;

    float* out = (float*)d_out;
    float* out_nodes = out;
    float* out_graph = out + (size_t)n * 64;

    float *buf0, *buf1;
    cudaGetSymbolAddress((void**)&buf0, g_buf04);
    cudaGetSymbolAddress((void**)&buf1, g_buf14);

    int nb = (n + 511) / 512;   // scan blocks (<=256)

    // NOTE: first k_gemm is launch #4 so the ncu window (which captures launch
    // #4) finally profiles the GEMM. Legal: gemm needs only x + g_dis (scan1);
    // it writes g_h, untouched by scan2/scan3/fill.
    k_init<<<(n + 255) / 256, 256>>>(out_graph, n);
    k_deg<<<(e / 2 + 255) / 256, 256>>>(ei, e);
    k_scan1<<<nb, 512>>>(batch, n);
    k_gemm<<<(n + 127) / 128, 128>>>(x, Ws[0], n);
    k_scan2<<<1, 256>>>(nb);
    k_scan3<<<(n + 255) / 256, 256>>>(n);
    k_fill<<<(e / 2 + 255) / 256, 256>>>(ei, e);

    const float* xin = x;
    float* xouts[3] = {buf0, buf1, out_nodes};
    for (int l = 0; l < 3; l++) {
        if (l > 0) k_gemm<<<(n + 127) / 128, 128>>>(xin, Ws[l], n);
        k_gather<<<(n + 15) / 16, 256>>>(bs[l], batch, xouts[l], n);
        k_graphacc<<<16, 256>>>(out_graph);
        xin = xouts[l];
    }
}